// round 1
// baseline (speedup 1.0000x reference)
#include <cuda_runtime.h>
#include <cstdint>
#include <cstdio>

#define B_ 64
#define S_ 64
#define P_ 32
#define D_ 512
#define E_ 512
#define H_ 512
#define H3_ 1536
#define A_ 256
#define NH_ 4
#define OUT_ 16
#define BS_ (B_*S_)

// d_out layout: out[64,16] | states[B,S,2H] | context[B,4096] | alpha_actv[B,NH,S]
#define STATES_OFF 1024
#define CONTEXT_OFF (1024 + BS_*2*H_)
#define ALPHA_OFF (CONTEXT_OFF + B_*NH_*2*H_)

#define GRU_NBLOCKS 128

// ---------------- scratch (device globals; no allocation allowed) -------------
__device__ float g_vec[BS_*D_];
__device__ float g_emb[BS_*E_];
__device__ float g_xg[2][BS_*H3_];
__device__ float g_h[2][2][B_*H_];
__device__ float g_m1[BS_*A_];
__device__ unsigned g_bar_count;
__device__ unsigned g_bar_gen;

// ---------------- f32x2 helpers (FFMA2: 2x fp32 FMA throughput) ---------------
__device__ __forceinline__ unsigned long long pk2(float x){
    unsigned long long r;
    asm("mov.b64 %0, {%1, %1};" : "=l"(r) : "f"(x));
    return r;
}
__device__ __forceinline__ void fma2(unsigned long long& d, unsigned long long a, unsigned long long b){
    asm("fma.rn.f32x2 %0, %1, %2, %0;" : "+l"(d) : "l"(a), "l"(b));
}
union U64F2 { unsigned long long u; float2 f; };

// ---------------- grid barrier (all GRU_NBLOCKS blocks co-resident) -----------
__device__ __forceinline__ void gbar(){
    __syncthreads();
    if (threadIdx.x == 0){
        __threadfence();
        unsigned g = *((volatile unsigned*)&g_bar_gen);
        if (atomicAdd(&g_bar_count, 1u) == GRU_NBLOCKS - 1u){
            g_bar_count = 0u;
            __threadfence();
            atomicExch(&g_bar_gen, g + 1u);
        } else {
            while (*((volatile unsigned*)&g_bar_gen) == g) { }
        }
        __threadfence();
    }
    __syncthreads();
}

// ---------------- fused conv + weighted-sum (reads inputs ONCE) ---------------
__global__ __launch_bounds__(256) void k_conv_vec(const float* __restrict__ inp,
                                                  const float* __restrict__ conv_w,
                                                  const float* __restrict__ conv_b){
    extern __shared__ float tile[];          // P_*D_ = 16384 floats = 64KB
    __shared__ float cw[D_];
    __shared__ float convp[P_];
    int bs = blockIdx.x;
    int tid = threadIdx.x;
    const float4* src4 = (const float4*)(inp + (size_t)bs*P_*D_);
    float4* t4 = (float4*)tile;
    for (int i = tid; i < D_; i += 256) cw[i] = conv_w[i];
    for (int i = tid; i < P_*D_/4; i += 256) t4[i] = src4[i];
    __syncthreads();
    int wid = tid >> 5, lane = tid & 31;
    float cb = conv_b[0];
    for (int p = wid; p < P_; p += 8){
        float s = 0.f;
        for (int d = lane; d < D_; d += 32) s += tile[p*D_+d]*cw[d];
        #pragma unroll
        for (int o = 16; o > 0; o >>= 1) s += __shfl_xor_sync(0xffffffffu, s, o);
        if (lane == 0) convp[p] = s + cb;
    }
    __syncthreads();
    for (int d = tid; d < D_; d += 256){
        float acc = 0.f;
        #pragma unroll
        for (int p = 0; p < P_; p++) acc += convp[p]*tile[p*D_+d];
        g_vec[(size_t)bs*D_ + d] = acc;
    }
}

// ---------------- SGEMM: C[M,N] = A[M,K] * Bw[N,K]^T (+bias)(clip) ------------
// permA: output row r reads input row (r%64)*64 + r/64 (the [B,S]->[S,B] transpose)
__global__ __launch_bounds__(256) void k_sgemm(const float* __restrict__ A,
                                               const float* __restrict__ Bw,
                                               float* __restrict__ C,
                                               int M, int N, int K,
                                               const float* __restrict__ bias,
                                               int doClip, int permA){
    __shared__ float As[2][8][128];
    __shared__ float Bs[2][8][128];
    int tid = threadIdx.x;
    int bx = blockIdx.x, by = blockIdx.y;
    int arow = tid >> 1;
    int acol = (tid & 1) * 4;
    int orow = by*128 + arow;
    int grow = permA ? ((orow & 63)*64 + (orow >> 6)) : orow;
    const float* Ap = A + (size_t)grow*K + acol;
    const float* Bp = Bw + (size_t)(bx*128 + arow)*K + acol;

    float4 av = *(const float4*)Ap;
    float4 bv = *(const float4*)Bp;
    As[0][acol+0][arow]=av.x; As[0][acol+1][arow]=av.y; As[0][acol+2][arow]=av.z; As[0][acol+3][arow]=av.w;
    Bs[0][acol+0][arow]=bv.x; Bs[0][acol+1][arow]=bv.y; Bs[0][acol+2][arow]=bv.z; Bs[0][acol+3][arow]=bv.w;
    __syncthreads();

    int tx = tid & 15, ty = tid >> 4;
    unsigned long long acc[8][4];
    #pragma unroll
    for (int i = 0; i < 8; i++){
        #pragma unroll
        for (int j = 0; j < 4; j++) acc[i][j] = 0ULL;
    }

    int nk = K >> 3;
    for (int kt = 0; kt < nk; kt++){
        int cur = kt & 1;
        if (kt + 1 < nk){
            av = *(const float4*)(Ap + (kt+1)*8);
            bv = *(const float4*)(Bp + (kt+1)*8);
        }
        #pragma unroll
        for (int k = 0; k < 8; k++){
            float4 a0 = *(const float4*)&As[cur][k][ty*4];
            float4 a1 = *(const float4*)&As[cur][k][64 + ty*4];
            unsigned long long b0 = *(const unsigned long long*)&Bs[cur][k][tx*4];
            unsigned long long b1 = *(const unsigned long long*)&Bs[cur][k][tx*4 + 2];
            unsigned long long b2 = *(const unsigned long long*)&Bs[cur][k][64 + tx*4];
            unsigned long long b3 = *(const unsigned long long*)&Bs[cur][k][64 + tx*4 + 2];
            float am[8] = {a0.x,a0.y,a0.z,a0.w,a1.x,a1.y,a1.z,a1.w};
            #pragma unroll
            for (int i = 0; i < 8; i++){
                unsigned long long pa = pk2(am[i]);
                fma2(acc[i][0], pa, b0);
                fma2(acc[i][1], pa, b1);
                fma2(acc[i][2], pa, b2);
                fma2(acc[i][3], pa, b3);
            }
        }
        if (kt + 1 < nk){
            int nxt = cur ^ 1;
            As[nxt][acol+0][arow]=av.x; As[nxt][acol+1][arow]=av.y; As[nxt][acol+2][arow]=av.z; As[nxt][acol+3][arow]=av.w;
            Bs[nxt][acol+0][arow]=bv.x; Bs[nxt][acol+1][arow]=bv.y; Bs[nxt][acol+2][arow]=bv.z; Bs[nxt][acol+3][arow]=bv.w;
            __syncthreads();
        }
    }

    int c0 = bx*128 + tx*4;
    float4 bv0 = make_float4(0.f,0.f,0.f,0.f), bv1 = bv0;
    if (bias){ bv0 = *(const float4*)&bias[c0]; bv1 = *(const float4*)&bias[c0+64]; }
    #pragma unroll
    for (int i = 0; i < 8; i++){
        int r = by*128 + ((i < 4) ? (ty*4 + i) : (64 + ty*4 + (i-4)));
        U64F2 u0,u1,u2,u3; u0.u=acc[i][0]; u1.u=acc[i][1]; u2.u=acc[i][2]; u3.u=acc[i][3];
        float4 o0 = make_float4(u0.f.x+bv0.x, u0.f.y+bv0.y, u1.f.x+bv0.z, u1.f.y+bv0.w);
        float4 o1 = make_float4(u2.f.x+bv1.x, u2.f.y+bv1.y, u3.f.x+bv1.z, u3.f.y+bv1.w);
        if (doClip){
            o0.x=fminf(fmaxf(o0.x,-1.f),1.f); o0.y=fminf(fmaxf(o0.y,-1.f),1.f);
            o0.z=fminf(fmaxf(o0.z,-1.f),1.f); o0.w=fminf(fmaxf(o0.w,-1.f),1.f);
            o1.x=fminf(fmaxf(o1.x,-1.f),1.f); o1.y=fminf(fmaxf(o1.y,-1.f),1.f);
            o1.z=fminf(fmaxf(o1.z,-1.f),1.f); o1.w=fminf(fmaxf(o1.w,-1.f),1.f);
        }
        *(float4*)&C[(size_t)r*N + c0] = o0;
        *(float4*)&C[(size_t)r*N + c0 + 64] = o1;
    }
}

// ---------------- persistent bidirectional GRU -------------------------------
// 128 blocks = 2 dirs x 64 j-chunks (JC=8). w_hh rows live in smem all 64 steps.
__global__ __launch_bounds__(256) void k_gru(const float* __restrict__ w_hh_f,
                                             const float* __restrict__ w_hh_b,
                                             const float* __restrict__ b_hh_f,
                                             const float* __restrict__ b_hh_b,
                                             float* __restrict__ states){
    extern __shared__ float smarr[];
    float* ws = smarr;              // 3*4*512*2 = 12288 floats (paired over j)
    float* hs = smarr + 12288;      // 64 k x 65 (padded) = 4160 floats
    int blk = blockIdx.x;
    int dir = blk >> 6, jc = blk & 63;
    int jbase = jc*8;
    const float* whh = dir ? w_hh_b : w_hh_f;
    const float* bhh = dir ? b_hh_b : b_hh_f;
    const float* xg = g_xg[dir];
    int tid = threadIdx.x;

    // load 24 w_hh rows into smem, interleaved so (j, j+1) is one 64-bit word
    for (int idx = tid; idx < 24*512; idx += 256){
        int r = idx >> 9, k = idx & 511;
        int g = r >> 3, jj = r & 7;
        int jp = jj >> 1, e = jj & 1;
        ws[((((g<<2)+jp)<<9) + k)*2 + e] = whh[(size_t)(g*H_ + jbase + jj)*H_ + k];
    }
    int b = tid & 63, jp = tid >> 6;
    int j0 = jbase + jp*2;
    float bhr0 = bhh[j0],        bhr1 = bhh[j0+1];
    float bhz0 = bhh[H_+j0],     bhz1 = bhh[H_+j0+1];
    float bhn0 = bhh[2*H_+j0],   bhn1 = bhh[2*H_+j0+1];
    g_h[dir][0][b*H_+j0] = 0.f; g_h[dir][0][b*H_+j0+1] = 0.f;
    gbar();

    const unsigned long long* w64 = (const unsigned long long*)ws;
    for (int t = 0; t < S_; t++){
        const float* hread = g_h[dir][t & 1];
        unsigned long long accr = 0ULL, accz = 0ULL, accn = 0ULL;
        for (int kc = 0; kc < H_; kc += 64){
            __syncthreads();
            for (int i = tid; i < 1024; i += 256){
                int bb = i >> 4, k4 = (i & 15) << 2;
                float4 v = *(const float4*)&hread[bb*H_ + kc + k4];
                hs[(k4+0)*65+bb]=v.x; hs[(k4+1)*65+bb]=v.y;
                hs[(k4+2)*65+bb]=v.z; hs[(k4+3)*65+bb]=v.w;
            }
            __syncthreads();
            int ir  = jp*512 + kc;
            int iz  = (4+jp)*512 + kc;
            int in2 = (8+jp)*512 + kc;
            #pragma unroll 8
            for (int k = 0; k < 64; k++){
                unsigned long long pa = pk2(hs[k*65 + b]);
                fma2(accr, pa, w64[ir + k]);
                fma2(accz, pa, w64[iz + k]);
                fma2(accn, pa, w64[in2 + k]);
            }
        }
        int tidx = dir ? (S_-1-t) : t;
        const float* x0 = xg + ((size_t)(tidx*B_ + b))*H3_;
        U64F2 ur, uz, un; ur.u = accr; uz.u = accz; un.u = accn;
        float hp0 = hread[b*H_+j0], hp1 = hread[b*H_+j0+1];
        float r0 = 1.f/(1.f+expf(-(x0[j0]      + ur.f.x + bhr0)));
        float r1 = 1.f/(1.f+expf(-(x0[j0+1]    + ur.f.y + bhr1)));
        float z0 = 1.f/(1.f+expf(-(x0[H_+j0]   + uz.f.x + bhz0)));
        float z1 = 1.f/(1.f+expf(-(x0[H_+j0+1] + uz.f.y + bhz1)));
        float n0 = tanhf(x0[2*H_+j0]   + r0*(un.f.x + bhn0));
        float n1 = tanhf(x0[2*H_+j0+1] + r1*(un.f.y + bhn1));
        float h0 = (1.f-z0)*n0 + z0*hp0;
        float h1 = (1.f-z1)*n1 + z1*hp1;
        float* hw = g_h[dir][(t & 1) ^ 1];
        hw[b*H_+j0] = h0; hw[b*H_+j0+1] = h1;
        size_t so = ((size_t)b*S_ + tidx)*(2*H_) + dir*H_ + j0;
        states[so] = h0; states[so+1] = h1;
        gbar();
    }
}

// ---------------- alpha = m1 @ att_w2^T, softmax over S -----------------------
__global__ __launch_bounds__(256) void k_alpha(const float* __restrict__ att_w2,
                                               float* __restrict__ alpha_out){
    __shared__ float w2s[NH_*A_];
    __shared__ float al[NH_*S_];
    int b = blockIdx.x, tid = threadIdx.x;
    for (int i = tid; i < NH_*A_; i += 256) w2s[i] = att_w2[i];
    __syncthreads();
    int s = tid >> 2, h = tid & 3;
    const float* m1r = g_m1 + ((size_t)(b*S_ + s))*A_;
    float acc = 0.f;
    #pragma unroll 4
    for (int k = 0; k < A_; k++) acc += m1r[k]*w2s[h*A_+k];
    al[h*S_+s] = acc;
    __syncthreads();
    int wid = tid >> 5, lane = tid & 31;
    if (wid < NH_){
        float v0 = al[wid*S_+lane], v1 = al[wid*S_+lane+32];
        float mx = fmaxf(v0, v1);
        #pragma unroll
        for (int o = 16; o > 0; o >>= 1) mx = fmaxf(mx, __shfl_xor_sync(0xffffffffu, mx, o));
        float e0 = expf(v0-mx), e1 = expf(v1-mx);
        float sm = e0 + e1;
        #pragma unroll
        for (int o = 16; o > 0; o >>= 1) sm += __shfl_xor_sync(0xffffffffu, sm, o);
        float inv = 1.f/sm;
        alpha_out[(b*NH_+wid)*S_ + lane]      = e0*inv;
        alpha_out[(b*NH_+wid)*S_ + lane + 32] = e1*inv;
    }
}

// ---------------- context = alpha @ states ------------------------------------
__global__ __launch_bounds__(512) void k_context(const float* __restrict__ states,
                                                 const float* __restrict__ alpha_in,
                                                 float* __restrict__ context){
    __shared__ float als[NH_*S_];
    int b = blockIdx.x, tid = threadIdx.x;
    if (tid < NH_*S_) als[tid] = alpha_in[b*NH_*S_ + tid];
    __syncthreads();
    float a0[NH_], a1[NH_];
    #pragma unroll
    for (int h = 0; h < NH_; h++){ a0[h] = 0.f; a1[h] = 0.f; }
    const float* st = states + (size_t)b*S_*2*H_;
    for (int s = 0; s < S_; s++){
        float v0 = st[s*2*H_ + tid];
        float v1 = st[s*2*H_ + H_ + tid];
        #pragma unroll
        for (int h = 0; h < NH_; h++){
            float a = als[h*S_+s];
            a0[h] += a*v0; a1[h] += a*v1;
        }
    }
    float* cb = context + (size_t)b*NH_*2*H_;
    #pragma unroll
    for (int h = 0; h < NH_; h++){
        cb[h*2*H_ + tid]      = a0[h];
        cb[h*2*H_ + H_ + tid] = a1[h];
    }
}

// ---------------- final linear + softmax --------------------------------------
__global__ __launch_bounds__(512) void k_final(const float* __restrict__ context,
                                               const float* __restrict__ lin_w,
                                               const float* __restrict__ lin_b,
                                               float* __restrict__ out){
    __shared__ float red[OUT_];
    int b = blockIdx.x, tid = threadIdx.x, w = tid >> 5, lane = tid & 31;
    const float* cx = context + (size_t)b*4096;
    const float* lw = lin_w + (size_t)w*4096;
    float acc = 0.f;
    for (int k = lane; k < 4096; k += 32) acc += cx[k]*lw[k];
    #pragma unroll
    for (int o = 16; o > 0; o >>= 1) acc += __shfl_xor_sync(0xffffffffu, acc, o);
    if (lane == 0) red[w] = acc + lin_b[w];
    __syncthreads();
    if (tid < 32){
        float v = (lane < OUT_) ? red[lane] : -1e30f;
        float mx = v;
        #pragma unroll
        for (int o = 16; o > 0; o >>= 1) mx = fmaxf(mx, __shfl_xor_sync(0xffffffffu, mx, o));
        float e = (lane < OUT_) ? expf(v - mx) : 0.f;
        float sm = e;
        #pragma unroll
        for (int o = 16; o > 0; o >>= 1) sm += __shfl_xor_sync(0xffffffffu, sm, o);
        if (lane < OUT_) out[b*OUT_ + lane] = e/sm;
    }
}

// ---------------- launch ------------------------------------------------------
extern "C" void kernel_launch(void* const* d_in, const int* in_sizes, int n_in,
                              void* d_out, int out_size){
    const float* inputs  = (const float*)d_in[0];
    const float* conv_w  = (const float*)d_in[2];
    const float* conv_b  = (const float*)d_in[3];
    const float* w_embed = (const float*)d_in[4];
    const float* w_ih_f  = (const float*)d_in[5];
    const float* w_hh_f  = (const float*)d_in[6];
    const float* b_ih_f  = (const float*)d_in[7];
    const float* b_hh_f  = (const float*)d_in[8];
    const float* w_ih_b  = (const float*)d_in[9];
    const float* w_hh_b  = (const float*)d_in[10];
    const float* b_ih_b  = (const float*)d_in[11];
    const float* b_hh_b  = (const float*)d_in[12];
    const float* att_w1  = (const float*)d_in[13];
    const float* att_w2  = (const float*)d_in[14];
    const float* lin_w   = (const float*)d_in[15];
    const float* lin_b   = (const float*)d_in[16];

    float* out     = (float*)d_out;
    float* states  = out + STATES_OFF;
    float* context = out + CONTEXT_OFF;
    float* alpha   = out + ALPHA_OFF;

    void *p_vec, *p_emb, *p_xg, *p_m1;
    cudaGetSymbolAddress(&p_vec, g_vec);
    cudaGetSymbolAddress(&p_emb, g_emb);
    cudaGetSymbolAddress(&p_xg,  g_xg);
    cudaGetSymbolAddress(&p_m1,  g_m1);
    float* vec = (float*)p_vec;
    float* emb = (float*)p_emb;
    float* xg0 = (float*)p_xg;
    float* xg1 = xg0 + (size_t)BS_*H3_;
    float* m1  = (float*)p_m1;

    const int conv_smem = P_*D_*4;                   // 65536
    const int gru_smem  = (12288 + 64*65)*4;         // 65792
    cudaFuncSetAttribute(k_conv_vec, cudaFuncAttributeMaxDynamicSharedMemorySize, conv_smem);
    cudaFuncSetAttribute(k_gru,      cudaFuncAttributeMaxDynamicSharedMemorySize, gru_smem);

    // 1) conv + weighted-sum (inputs read once)
    k_conv_vec<<<BS_, 256, conv_smem>>>(inputs, conv_w, conv_b);
    // 2) emb = clip(vec @ w_embed^T)
    k_sgemm<<<dim3(E_/128, BS_/128), 256>>>(vec, w_embed, emb, BS_, E_, D_, nullptr, 1, 0);
    // 3) xg = emb([S,B] permuted) @ w_ih^T + b_ih, both directions
    k_sgemm<<<dim3(H3_/128, BS_/128), 256>>>(emb, w_ih_f, xg0, BS_, H3_, E_, b_ih_f, 0, 1);
    k_sgemm<<<dim3(H3_/128, BS_/128), 256>>>(emb, w_ih_b, xg1, BS_, H3_, E_, b_ih_b, 0, 1);
    // 4) persistent bidirectional GRU -> states (written straight into d_out)
    k_gru<<<GRU_NBLOCKS, 256, gru_smem>>>(w_hh_f, w_hh_b, b_hh_f, b_hh_b, states);
    // 5) m1 = clip(states @ att_w1^T)
    k_sgemm<<<dim3(A_/128, BS_/128), 256>>>(states, att_w1, m1, BS_, A_, 2*H_, nullptr, 1, 0);
    // 6) alpha = softmax_S(m1 @ att_w2^T), transposed to [B,NH,S]
    k_alpha<<<B_, 256>>>(att_w2, alpha);
    // 7) context
    k_context<<<B_, 512>>>(states, alpha, context);
    // 8) out = softmax(context @ lin_w^T + lin_b)
    k_final<<<B_, 512>>>(context, lin_w, lin_b, out);
}

// round 2
// speedup vs baseline: 1.5370x; 1.5370x over previous
#include <cuda_runtime.h>
#include <cstdint>
#include <cstdio>

#define B_ 64
#define S_ 64
#define P_ 32
#define D_ 512
#define E_ 512
#define H_ 512
#define H3_ 1536
#define A_ 256
#define NH_ 4
#define OUT_ 16
#define BS_ (B_*S_)

// d_out layout: out[64,16] | states[B,S,2H] | context[B,4096] | alpha_actv[B,NH,S]
#define STATES_OFF 1024
#define CONTEXT_OFF (1024 + BS_*2*H_)
#define ALPHA_OFF (CONTEXT_OFF + B_*NH_*2*H_)

// ---------------- scratch (device globals; no allocation allowed) -------------
__device__ float g_vec[BS_*D_];
__device__ float g_emb[BS_*E_];
__device__ float g_xg[2][BS_*H3_];
__device__ float g_h2[2][2][B_*H_];     // [dir][buf][b*H+j]
__device__ float g_m1[BS_*A_];
__device__ unsigned g_cnt[2][32];       // per-dir barrier count (separate lines)
__device__ unsigned g_gen[2][32];       // per-dir barrier generation

typedef unsigned long long ull;

// ---------------- f32x2 helpers (FFMA2: 2x fp32 FMA throughput) ---------------
__device__ __forceinline__ ull pk2(float x){
    ull r;
    asm("mov.b64 %0, {%1, %1};" : "=l"(r) : "f"(x));
    return r;
}
__device__ __forceinline__ void fma2(ull& d, ull a, ull b){
    asm("fma.rn.f32x2 %0, %1, %2, %0;" : "+l"(d) : "l"(a), "l"(b));
}
union U64F2 { ull u; float2 f; };

// ---------------- per-direction grid barrier (64 blocks each) -----------------
__device__ __forceinline__ void gbar_dir(int dir){
    __syncthreads();
    if (threadIdx.x == 0){
        volatile unsigned* gen = &g_gen[dir][0];
        __threadfence();
        unsigned g = *gen;
        if (atomicAdd(&g_cnt[dir][0], 1u) == 63u){
            g_cnt[dir][0] = 0u;
            __threadfence();
            atomicExch((unsigned*)&g_gen[dir][0], g + 1u);
        } else {
            while (*gen == g) { }
        }
        __threadfence();
    }
    __syncthreads();
}

// ---------------- fused conv + weighted-sum (reads inputs ONCE) ---------------
__global__ __launch_bounds__(256) void k_conv_vec(const float* __restrict__ inp,
                                                  const float* __restrict__ conv_w,
                                                  const float* __restrict__ conv_b){
    extern __shared__ float tile[];          // P_*D_ = 16384 floats = 64KB
    __shared__ float cw[D_];
    __shared__ float convp[P_];
    int bs = blockIdx.x;
    int tid = threadIdx.x;
    const float4* src4 = (const float4*)(inp + (size_t)bs*P_*D_);
    float4* t4 = (float4*)tile;
    for (int i = tid; i < D_; i += 256) cw[i] = conv_w[i];
    for (int i = tid; i < P_*D_/4; i += 256) t4[i] = src4[i];
    __syncthreads();
    int wid = tid >> 5, lane = tid & 31;
    float cb = conv_b[0];
    for (int p = wid; p < P_; p += 8){
        float s = 0.f;
        for (int d = lane; d < D_; d += 32) s += tile[p*D_+d]*cw[d];
        #pragma unroll
        for (int o = 16; o > 0; o >>= 1) s += __shfl_xor_sync(0xffffffffu, s, o);
        if (lane == 0) convp[p] = s + cb;
    }
    __syncthreads();
    for (int d = tid; d < D_; d += 256){
        float acc = 0.f;
        #pragma unroll
        for (int p = 0; p < P_; p++) acc += convp[p]*tile[p*D_+d];
        g_vec[(size_t)bs*D_ + d] = acc;
    }
}

// ---------------- SGEMM: C[M,N] = A[M,K] * Bw[N,K]^T (+bias)(clip) ------------
// permA: output row r reads input row (r%64)*64 + r/64 (the [B,S]->[S,B] transpose)
__global__ __launch_bounds__(256, 2) void k_sgemm(const float* __restrict__ A,
                                                  const float* __restrict__ Bw,
                                                  float* __restrict__ C,
                                                  int M, int N, int K,
                                                  const float* __restrict__ bias,
                                                  int doClip, int permA){
    __shared__ float As[2][8][128];
    __shared__ float Bs[2][8][128];
    int tid = threadIdx.x;
    int bx = blockIdx.x, by = blockIdx.y;
    int arow = tid >> 1;
    int acol = (tid & 1) * 4;
    int orow = by*128 + arow;
    int grow = permA ? ((orow & 63)*64 + (orow >> 6)) : orow;
    const float* Ap = A + (size_t)grow*K + acol;
    const float* Bp = Bw + (size_t)(bx*128 + arow)*K + acol;

    float4 av = *(const float4*)Ap;
    float4 bv = *(const float4*)Bp;
    As[0][acol+0][arow]=av.x; As[0][acol+1][arow]=av.y; As[0][acol+2][arow]=av.z; As[0][acol+3][arow]=av.w;
    Bs[0][acol+0][arow]=bv.x; Bs[0][acol+1][arow]=bv.y; Bs[0][acol+2][arow]=bv.z; Bs[0][acol+3][arow]=bv.w;
    __syncthreads();

    int tx = tid & 15, ty = tid >> 4;
    ull acc[8][4];
    #pragma unroll
    for (int i = 0; i < 8; i++){
        #pragma unroll
        for (int j = 0; j < 4; j++) acc[i][j] = 0ULL;
    }

    int nk = K >> 3;
    for (int kt = 0; kt < nk; kt++){
        int cur = kt & 1;
        if (kt + 1 < nk){
            av = *(const float4*)(Ap + (kt+1)*8);
            bv = *(const float4*)(Bp + (kt+1)*8);
        }
        #pragma unroll
        for (int k = 0; k < 8; k++){
            float4 a0 = *(const float4*)&As[cur][k][ty*4];
            float4 a1 = *(const float4*)&As[cur][k][64 + ty*4];
            ull b0 = *(const ull*)&Bs[cur][k][tx*4];
            ull b1 = *(const ull*)&Bs[cur][k][tx*4 + 2];
            ull b2 = *(const ull*)&Bs[cur][k][64 + tx*4];
            ull b3 = *(const ull*)&Bs[cur][k][64 + tx*4 + 2];
            float am[8] = {a0.x,a0.y,a0.z,a0.w,a1.x,a1.y,a1.z,a1.w};
            #pragma unroll
            for (int i = 0; i < 8; i++){
                ull pa = pk2(am[i]);
                fma2(acc[i][0], pa, b0);
                fma2(acc[i][1], pa, b1);
                fma2(acc[i][2], pa, b2);
                fma2(acc[i][3], pa, b3);
            }
        }
        if (kt + 1 < nk){
            int nxt = cur ^ 1;
            As[nxt][acol+0][arow]=av.x; As[nxt][acol+1][arow]=av.y; As[nxt][acol+2][arow]=av.z; As[nxt][acol+3][arow]=av.w;
            Bs[nxt][acol+0][arow]=bv.x; Bs[nxt][acol+1][arow]=bv.y; Bs[nxt][acol+2][arow]=bv.z; Bs[nxt][acol+3][arow]=bv.w;
            __syncthreads();
        }
    }

    int c0 = bx*128 + tx*4;
    float4 bv0 = make_float4(0.f,0.f,0.f,0.f), bv1 = bv0;
    if (bias){ bv0 = *(const float4*)&bias[c0]; bv1 = *(const float4*)&bias[c0+64]; }
    #pragma unroll
    for (int i = 0; i < 8; i++){
        int r = by*128 + ((i < 4) ? (ty*4 + i) : (64 + ty*4 + (i-4)));
        U64F2 u0,u1,u2,u3; u0.u=acc[i][0]; u1.u=acc[i][1]; u2.u=acc[i][2]; u3.u=acc[i][3];
        float4 o0 = make_float4(u0.f.x+bv0.x, u0.f.y+bv0.y, u1.f.x+bv0.z, u1.f.y+bv0.w);
        float4 o1 = make_float4(u2.f.x+bv1.x, u2.f.y+bv1.y, u3.f.x+bv1.z, u3.f.y+bv1.w);
        if (doClip){
            o0.x=fminf(fmaxf(o0.x,-1.f),1.f); o0.y=fminf(fmaxf(o0.y,-1.f),1.f);
            o0.z=fminf(fmaxf(o0.z,-1.f),1.f); o0.w=fminf(fmaxf(o0.w,-1.f),1.f);
            o1.x=fminf(fmaxf(o1.x,-1.f),1.f); o1.y=fminf(fmaxf(o1.y,-1.f),1.f);
            o1.z=fminf(fmaxf(o1.z,-1.f),1.f); o1.w=fminf(fmaxf(o1.w,-1.f),1.f);
        }
        *(float4*)&C[(size_t)r*N + c0] = o0;
        *(float4*)&C[(size_t)r*N + c0 + 64] = o1;
    }
}

// ---------------- persistent bidirectional GRU v2 -----------------------------
// 128 blocks = 2 dirs x 64 j-chunks (8 j each). Weights resident in smem (48KB),
// full hidden state staged per step into a swizzled smem image (128KB).
// Inner loop: 7 LDS128 + 12 FFMA2 per 4-k quad, zero packing movs.
__global__ __launch_bounds__(256) void k_gru(const float* __restrict__ w_hh_f,
                                             const float* __restrict__ w_hh_b,
                                             const float* __restrict__ b_hh_f,
                                             const float* __restrict__ b_hh_b,
                                             float* __restrict__ states){
    extern __shared__ float sm[];
    float* ws = sm;                                 // 24*512 = 12288 floats (48KB)
    float4* hs4 = (float4*)(sm + 12288);            // 64 b x 128 quads (128KB)

    int blk = blockIdx.x;
    int dir = blk >> 6, jc = blk & 63;
    int jbase = jc*8;
    const float* whh = dir ? w_hh_b : w_hh_f;
    const float* bhh = dir ? b_hh_b : b_hh_f;
    const float* xg = g_xg[dir];
    int tid = threadIdx.x;

    // load 24 weight rows (rows: g*8 + jj), coalesced float4 copies
    {
        const float4* w4 = (const float4*)whh;
        float4* d4 = (float4*)ws;
        for (int idx = tid; idx < 24*128; idx += 256){
            int r = idx >> 7;                // 0..23
            int k4 = idx & 127;
            int g = r >> 3, jj = r & 7;
            d4[r*128 + k4] = w4[(size_t)(g*H_ + jbase + jj)*128 + k4];
        }
    }

    int b = tid & 63, jp = tid >> 6;
    int j0 = jbase + jp*2;
    unsigned sb = b & 7;                     // swizzle key
    float2 bhr = *(const float2*)&bhh[j0];
    float2 bhz = *(const float2*)&bhh[H_+j0];
    float2 bhn = *(const float2*)&bhh[2*H_+j0];

    // zero initial hidden state (buffer 0), collectively over all blocks of dir
    *(float2*)&g_h2[dir][0][b*H_ + j0] = make_float2(0.f, 0.f);
    gbar_dir(dir);

    // weight row pointers for this thread's (jp): rows jp*2+e + 8*g
    const ulonglong2* wr0 = (const ulonglong2*)(ws + jp*1024);
    const ulonglong2* wr1 = (const ulonglong2*)(ws + jp*1024 + 512);
    const ulonglong2* wz0 = (const ulonglong2*)(ws + jp*1024 + 4096);
    const ulonglong2* wz1 = (const ulonglong2*)(ws + jp*1024 + 4608);
    const ulonglong2* wn0 = (const ulonglong2*)(ws + jp*1024 + 8192);
    const ulonglong2* wn1 = (const ulonglong2*)(ws + jp*1024 + 8704);
    const ulonglong2* hrow = (const ulonglong2*)(hs4 + b*128);

    for (int t = 0; t < S_; t++){
        // prefetch xg for this step (independent of h; overlaps staging)
        int tidx = dir ? (S_-1-t) : t;
        const float* x0 = xg + ((size_t)(tidx*B_ + b))*H3_;
        float2 xr = *(const float2*)&x0[j0];
        float2 xz = *(const float2*)&x0[H_+j0];
        float2 xn = *(const float2*)&x0[2*H_+j0];

        // stage full hidden state (coalesced LDG128 -> swizzled STS128)
        const float4* hr4 = (const float4*)g_h2[dir][t & 1];
        #pragma unroll
        for (int i = 0; i < 32; i++){
            int idx = tid + i*256;
            int bb = idx >> 7, kq = idx & 127;
            hs4[bb*128 + (kq ^ (bb & 7))] = hr4[bb*128 + kq];
        }
        __syncthreads();

        ull accr0=0ULL, accr1=0ULL, accz0=0ULL, accz1=0ULL, accn0=0ULL, accn1=0ULL;
        #pragma unroll 8
        for (int kq = 0; kq < 128; kq++){
            ulonglong2 h2 = hrow[kq ^ sb];
            ulonglong2 w;
            w = wr0[kq]; fma2(accr0, h2.x, w.x); fma2(accr0, h2.y, w.y);
            w = wr1[kq]; fma2(accr1, h2.x, w.x); fma2(accr1, h2.y, w.y);
            w = wz0[kq]; fma2(accz0, h2.x, w.x); fma2(accz0, h2.y, w.y);
            w = wz1[kq]; fma2(accz1, h2.x, w.x); fma2(accz1, h2.y, w.y);
            w = wn0[kq]; fma2(accn0, h2.x, w.x); fma2(accn0, h2.y, w.y);
            w = wn1[kq]; fma2(accn1, h2.x, w.x); fma2(accn1, h2.y, w.y);
        }

        // previous h for this thread's two outputs (from swizzled smem image)
        int kqj = j0 >> 2;
        const float* hq = (const float*)(hs4 + b*128 + (kqj ^ sb));
        float hp0 = hq[j0 & 3], hp1 = hq[(j0 & 3) + 1];

        U64F2 u;
        u.u = accr0; float sr0 = u.f.x + u.f.y;
        u.u = accr1; float sr1 = u.f.x + u.f.y;
        u.u = accz0; float sz0 = u.f.x + u.f.y;
        u.u = accz1; float sz1 = u.f.x + u.f.y;
        u.u = accn0; float sn0 = u.f.x + u.f.y;
        u.u = accn1; float sn1 = u.f.x + u.f.y;

        float r0 = 1.f/(1.f+expf(-(xr.x + sr0 + bhr.x)));
        float r1 = 1.f/(1.f+expf(-(xr.y + sr1 + bhr.y)));
        float z0 = 1.f/(1.f+expf(-(xz.x + sz0 + bhz.x)));
        float z1 = 1.f/(1.f+expf(-(xz.y + sz1 + bhz.y)));
        float n0 = tanhf(xn.x + r0*(sn0 + bhn.x));
        float n1 = tanhf(xn.y + r1*(sn1 + bhn.y));
        float h0 = (1.f-z0)*n0 + z0*hp0;
        float h1 = (1.f-z1)*n1 + z1*hp1;

        *(float2*)&g_h2[dir][(t & 1) ^ 1][b*H_ + j0] = make_float2(h0, h1);
        size_t so = ((size_t)b*S_ + tidx)*(2*H_) + dir*H_ + j0;
        *(float2*)&states[so] = make_float2(h0, h1);

        gbar_dir(dir);
    }
}

// ---------------- alpha = m1 @ att_w2^T, softmax over S -----------------------
__global__ __launch_bounds__(256) void k_alpha(const float* __restrict__ att_w2,
                                               float* __restrict__ alpha_out){
    __shared__ float w2s[NH_*A_];
    __shared__ float al[NH_*S_];
    int b = blockIdx.x, tid = threadIdx.x;
    for (int i = tid; i < NH_*A_; i += 256) w2s[i] = att_w2[i];
    __syncthreads();
    int s = tid >> 2, h = tid & 3;
    const float* m1r = g_m1 + ((size_t)(b*S_ + s))*A_;
    float acc = 0.f;
    #pragma unroll 4
    for (int k = 0; k < A_; k++) acc += m1r[k]*w2s[h*A_+k];
    al[h*S_+s] = acc;
    __syncthreads();
    int wid = tid >> 5, lane = tid & 31;
    if (wid < NH_){
        float v0 = al[wid*S_+lane], v1 = al[wid*S_+lane+32];
        float mx = fmaxf(v0, v1);
        #pragma unroll
        for (int o = 16; o > 0; o >>= 1) mx = fmaxf(mx, __shfl_xor_sync(0xffffffffu, mx, o));
        float e0 = expf(v0-mx), e1 = expf(v1-mx);
        float sm = e0 + e1;
        #pragma unroll
        for (int o = 16; o > 0; o >>= 1) sm += __shfl_xor_sync(0xffffffffu, sm, o);
        float inv = 1.f/sm;
        alpha_out[(b*NH_+wid)*S_ + lane]      = e0*inv;
        alpha_out[(b*NH_+wid)*S_ + lane + 32] = e1*inv;
    }
}

// ---------------- context = alpha @ states ------------------------------------
__global__ __launch_bounds__(512) void k_context(const float* __restrict__ states,
                                                 const float* __restrict__ alpha_in,
                                                 float* __restrict__ context){
    __shared__ float als[NH_*S_];
    int b = blockIdx.x, tid = threadIdx.x;
    if (tid < NH_*S_) als[tid] = alpha_in[b*NH_*S_ + tid];
    __syncthreads();
    float a0[NH_], a1[NH_];
    #pragma unroll
    for (int h = 0; h < NH_; h++){ a0[h] = 0.f; a1[h] = 0.f; }
    const float* st = states + (size_t)b*S_*2*H_;
    for (int s = 0; s < S_; s++){
        float v0 = st[s*2*H_ + tid];
        float v1 = st[s*2*H_ + H_ + tid];
        #pragma unroll
        for (int h = 0; h < NH_; h++){
            float a = als[h*S_+s];
            a0[h] += a*v0; a1[h] += a*v1;
        }
    }
    float* cb = context + (size_t)b*NH_*2*H_;
    #pragma unroll
    for (int h = 0; h < NH_; h++){
        cb[h*2*H_ + tid]      = a0[h];
        cb[h*2*H_ + H_ + tid] = a1[h];
    }
}

// ---------------- final linear + softmax --------------------------------------
__global__ __launch_bounds__(512) void k_final(const float* __restrict__ context,
                                               const float* __restrict__ lin_w,
                                               const float* __restrict__ lin_b,
                                               float* __restrict__ out){
    __shared__ float red[OUT_];
    int b = blockIdx.x, tid = threadIdx.x, w = tid >> 5, lane = tid & 31;
    const float* cx = context + (size_t)b*4096;
    const float* lw = lin_w + (size_t)w*4096;
    float acc = 0.f;
    for (int k = lane; k < 4096; k += 32) acc += cx[k]*lw[k];
    #pragma unroll
    for (int o = 16; o > 0; o >>= 1) acc += __shfl_xor_sync(0xffffffffu, acc, o);
    if (lane == 0) red[w] = acc + lin_b[w];
    __syncthreads();
    if (tid < 32){
        float v = (lane < OUT_) ? red[lane] : -1e30f;
        float mx = v;
        #pragma unroll
        for (int o = 16; o > 0; o >>= 1) mx = fmaxf(mx, __shfl_xor_sync(0xffffffffu, mx, o));
        float e = (lane < OUT_) ? expf(v - mx) : 0.f;
        float sm = e;
        #pragma unroll
        for (int o = 16; o > 0; o >>= 1) sm += __shfl_xor_sync(0xffffffffu, sm, o);
        if (lane < OUT_) out[b*OUT_ + lane] = e/sm;
    }
}

// ---------------- launch ------------------------------------------------------
extern "C" void kernel_launch(void* const* d_in, const int* in_sizes, int n_in,
                              void* d_out, int out_size){
    const float* inputs  = (const float*)d_in[0];
    const float* conv_w  = (const float*)d_in[2];
    const float* conv_b  = (const float*)d_in[3];
    const float* w_embed = (const float*)d_in[4];
    const float* w_ih_f  = (const float*)d_in[5];
    const float* w_hh_f  = (const float*)d_in[6];
    const float* b_ih_f  = (const float*)d_in[7];
    const float* b_hh_f  = (const float*)d_in[8];
    const float* w_ih_b  = (const float*)d_in[9];
    const float* w_hh_b  = (const float*)d_in[10];
    const float* b_ih_b  = (const float*)d_in[11];
    const float* b_hh_b  = (const float*)d_in[12];
    const float* att_w1  = (const float*)d_in[13];
    const float* att_w2  = (const float*)d_in[14];
    const float* lin_w   = (const float*)d_in[15];
    const float* lin_b   = (const float*)d_in[16];

    float* out     = (float*)d_out;
    float* states  = out + STATES_OFF;
    float* context = out + CONTEXT_OFF;
    float* alpha   = out + ALPHA_OFF;

    void *p_vec, *p_emb, *p_xg, *p_m1;
    cudaGetSymbolAddress(&p_vec, g_vec);
    cudaGetSymbolAddress(&p_emb, g_emb);
    cudaGetSymbolAddress(&p_xg,  g_xg);
    cudaGetSymbolAddress(&p_m1,  g_m1);
    float* vec = (float*)p_vec;
    float* emb = (float*)p_emb;
    float* xg0 = (float*)p_xg;
    float* xg1 = xg0 + (size_t)BS_*H3_;
    float* m1  = (float*)p_m1;

    const int conv_smem = P_*D_*4;                     // 65536
    const int gru_smem  = (12288 + 64*128*4)*4;        // 48KB + 128KB = 180224
    cudaFuncSetAttribute(k_conv_vec, cudaFuncAttributeMaxDynamicSharedMemorySize, conv_smem);
    cudaFuncSetAttribute(k_gru,      cudaFuncAttributeMaxDynamicSharedMemorySize, gru_smem);

    // 1) conv + weighted-sum (inputs read once)
    k_conv_vec<<<BS_, 256, conv_smem>>>(inputs, conv_w, conv_b);
    // 2) emb = clip(vec @ w_embed^T)
    k_sgemm<<<dim3(E_/128, BS_/128), 256>>>(vec, w_embed, emb, BS_, E_, D_, nullptr, 1, 0);
    // 3) xg = emb([S,B] permuted) @ w_ih^T + b_ih, both directions
    k_sgemm<<<dim3(H3_/128, BS_/128), 256>>>(emb, w_ih_f, xg0, BS_, H3_, E_, b_ih_f, 0, 1);
    k_sgemm<<<dim3(H3_/128, BS_/128), 256>>>(emb, w_ih_b, xg1, BS_, H3_, E_, b_ih_b, 0, 1);
    // 4) persistent bidirectional GRU -> states (written straight into d_out)
    k_gru<<<128, 256, gru_smem>>>(w_hh_f, w_hh_b, b_hh_f, b_hh_b, states);
    // 5) m1 = clip(states @ att_w1^T)
    k_sgemm<<<dim3(A_/128, BS_/128), 256>>>(states, att_w1, m1, BS_, A_, 2*H_, nullptr, 1, 0);
    // 6) alpha = softmax_S(m1 @ att_w2^T), transposed to [B,NH,S]
    k_alpha<<<B_, 256>>>(att_w2, alpha);
    // 7) context
    k_context<<<B_, 512>>>(states, alpha, context);
    // 8) out = softmax(context @ lin_w^T + lin_b)
    k_final<<<B_, 512>>>(context, lin_w, lin_b, out);
}

// round 3
// speedup vs baseline: 1.5939x; 1.0370x over previous
#include <cuda_runtime.h>
#include <cstdint>
#include <cstdio>

#define B_ 64
#define S_ 64
#define P_ 32
#define D_ 512
#define E_ 512
#define H_ 512
#define H3_ 1536
#define A_ 256
#define NH_ 4
#define OUT_ 16
#define BS_ (B_*S_)

// d_out layout: out[64,16] | states[B,S,2H] | context[B,4096] | alpha_actv[B,NH,S]
#define STATES_OFF 1024
#define CONTEXT_OFF (1024 + BS_*2*H_)
#define ALPHA_OFF (CONTEXT_OFF + B_*NH_*2*H_)

// ---------------- scratch (device globals; no allocation allowed) -------------
__device__ float g_vec[BS_*D_];
__device__ float g_emb[BS_*E_];
__device__ float g_xg[2][BS_*H3_];
__device__ float g_h2[2][2][B_*H_];     // [dir][buf][b*H+j]
__device__ float g_m1[BS_*A_];
__device__ volatile unsigned g_cnt4[4][32];   // 4 barrier groups, padded
__device__ volatile unsigned g_gen4[4][32];

typedef unsigned long long ull;

// ---------------- f32x2 helpers (FFMA2: 2x fp32 FMA throughput) ---------------
__device__ __forceinline__ ull pk2(float x){
    ull r;
    asm("mov.b64 %0, {%1, %1};" : "=l"(r) : "f"(x));
    return r;
}
__device__ __forceinline__ void fma2(ull& d, ull a, ull b){
    asm("fma.rn.f32x2 %0, %1, %2, %0;" : "+l"(d) : "l"(a), "l"(b));
}
union U64F2 { ull u; float2 f; };

// ---------------- group grid barrier (32 blocks per group) --------------------
__device__ __forceinline__ void gbar_grp(int grp){
    __syncthreads();
    if (threadIdx.x == 0){
        __threadfence();
        unsigned g = g_gen4[grp][0];
        if (atomicAdd((unsigned*)&g_cnt4[grp][0], 1u) == 31u){
            g_cnt4[grp][0] = 0u;
            __threadfence();
            atomicExch((unsigned*)&g_gen4[grp][0], g + 1u);
        } else {
            while (g_gen4[grp][0] == g) { }
        }
        __threadfence();
    }
    __syncthreads();
}

// ---------------- fused conv + weighted-sum (reads inputs ONCE) ---------------
__global__ __launch_bounds__(256) void k_conv_vec(const float* __restrict__ inp,
                                                  const float* __restrict__ conv_w,
                                                  const float* __restrict__ conv_b){
    extern __shared__ float tile[];          // P_*D_ = 16384 floats = 64KB
    __shared__ float cw[D_];
    __shared__ float convp[P_];
    int bs = blockIdx.x;
    int tid = threadIdx.x;
    const float4* src4 = (const float4*)(inp + (size_t)bs*P_*D_);
    float4* t4 = (float4*)tile;
    for (int i = tid; i < D_; i += 256) cw[i] = conv_w[i];
    for (int i = tid; i < P_*D_/4; i += 256) t4[i] = src4[i];
    __syncthreads();
    int wid = tid >> 5, lane = tid & 31;
    float cb = conv_b[0];
    for (int p = wid; p < P_; p += 8){
        float s = 0.f;
        for (int d = lane; d < D_; d += 32) s += tile[p*D_+d]*cw[d];
        #pragma unroll
        for (int o = 16; o > 0; o >>= 1) s += __shfl_xor_sync(0xffffffffu, s, o);
        if (lane == 0) convp[p] = s + cb;
    }
    __syncthreads();
    for (int d = tid; d < D_; d += 256){
        float acc = 0.f;
        #pragma unroll
        for (int p = 0; p < P_; p++) acc += convp[p]*tile[p*D_+d];
        g_vec[(size_t)bs*D_ + d] = acc;
    }
}

// ---------------- SGEMM: C[M,N] = A[M,K] * Bw[N,K]^T (+bias)(clip) ------------
// permA: output row r reads input row (r%64)*64 + r/64 (the [B,S]->[S,B] transpose)
__global__ __launch_bounds__(256, 2) void k_sgemm(const float* __restrict__ A,
                                                  const float* __restrict__ Bw,
                                                  float* __restrict__ C,
                                                  int M, int N, int K,
                                                  const float* __restrict__ bias,
                                                  int doClip, int permA){
    __shared__ float As[2][8][128];
    __shared__ float Bs[2][8][128];
    int tid = threadIdx.x;
    int bx = blockIdx.x, by = blockIdx.y;
    int arow = tid >> 1;
    int acol = (tid & 1) * 4;
    int orow = by*128 + arow;
    int grow = permA ? ((orow & 63)*64 + (orow >> 6)) : orow;
    const float* Ap = A + (size_t)grow*K + acol;
    const float* Bp = Bw + (size_t)(bx*128 + arow)*K + acol;

    float4 av = *(const float4*)Ap;
    float4 bv = *(const float4*)Bp;
    As[0][acol+0][arow]=av.x; As[0][acol+1][arow]=av.y; As[0][acol+2][arow]=av.z; As[0][acol+3][arow]=av.w;
    Bs[0][acol+0][arow]=bv.x; Bs[0][acol+1][arow]=bv.y; Bs[0][acol+2][arow]=bv.z; Bs[0][acol+3][arow]=bv.w;
    __syncthreads();

    int tx = tid & 15, ty = tid >> 4;
    ull acc[8][4];
    #pragma unroll
    for (int i = 0; i < 8; i++){
        #pragma unroll
        for (int j = 0; j < 4; j++) acc[i][j] = 0ULL;
    }

    int nk = K >> 3;
    for (int kt = 0; kt < nk; kt++){
        int cur = kt & 1;
        if (kt + 1 < nk){
            av = *(const float4*)(Ap + (kt+1)*8);
            bv = *(const float4*)(Bp + (kt+1)*8);
        }
        #pragma unroll
        for (int k = 0; k < 8; k++){
            float4 a0 = *(const float4*)&As[cur][k][ty*4];
            float4 a1 = *(const float4*)&As[cur][k][64 + ty*4];
            ull b0 = *(const ull*)&Bs[cur][k][tx*4];
            ull b1 = *(const ull*)&Bs[cur][k][tx*4 + 2];
            ull b2 = *(const ull*)&Bs[cur][k][64 + tx*4];
            ull b3 = *(const ull*)&Bs[cur][k][64 + tx*4 + 2];
            float am[8] = {a0.x,a0.y,a0.z,a0.w,a1.x,a1.y,a1.z,a1.w};
            #pragma unroll
            for (int i = 0; i < 8; i++){
                ull pa = pk2(am[i]);
                fma2(acc[i][0], pa, b0);
                fma2(acc[i][1], pa, b1);
                fma2(acc[i][2], pa, b2);
                fma2(acc[i][3], pa, b3);
            }
        }
        if (kt + 1 < nk){
            int nxt = cur ^ 1;
            As[nxt][acol+0][arow]=av.x; As[nxt][acol+1][arow]=av.y; As[nxt][acol+2][arow]=av.z; As[nxt][acol+3][arow]=av.w;
            Bs[nxt][acol+0][arow]=bv.x; Bs[nxt][acol+1][arow]=bv.y; Bs[nxt][acol+2][arow]=bv.z; Bs[nxt][acol+3][arow]=bv.w;
            __syncthreads();
        }
    }

    int c0 = bx*128 + tx*4;
    float4 bv0 = make_float4(0.f,0.f,0.f,0.f), bv1 = bv0;
    if (bias){ bv0 = *(const float4*)&bias[c0]; bv1 = *(const float4*)&bias[c0+64]; }
    #pragma unroll
    for (int i = 0; i < 8; i++){
        int r = by*128 + ((i < 4) ? (ty*4 + i) : (64 + ty*4 + (i-4)));
        U64F2 u0,u1,u2,u3; u0.u=acc[i][0]; u1.u=acc[i][1]; u2.u=acc[i][2]; u3.u=acc[i][3];
        float4 o0 = make_float4(u0.f.x+bv0.x, u0.f.y+bv0.y, u1.f.x+bv0.z, u1.f.y+bv0.w);
        float4 o1 = make_float4(u2.f.x+bv1.x, u2.f.y+bv1.y, u3.f.x+bv1.z, u3.f.y+bv1.w);
        if (doClip){
            o0.x=fminf(fmaxf(o0.x,-1.f),1.f); o0.y=fminf(fmaxf(o0.y,-1.f),1.f);
            o0.z=fminf(fmaxf(o0.z,-1.f),1.f); o0.w=fminf(fmaxf(o0.w,-1.f),1.f);
            o1.x=fminf(fmaxf(o1.x,-1.f),1.f); o1.y=fminf(fmaxf(o1.y,-1.f),1.f);
            o1.z=fminf(fmaxf(o1.z,-1.f),1.f); o1.w=fminf(fmaxf(o1.w,-1.f),1.f);
        }
        *(float4*)&C[(size_t)r*N + c0] = o0;
        *(float4*)&C[(size_t)r*N + c0 + 64] = o1;
    }
}

// ---------------- persistent bidirectional GRU v3 -----------------------------
__global__ __launch_bounds__(128) void k_gru(const float* __restrict__ w_hh_f,
                                             const float* __restrict__ w_hh_b,
                                             const float* __restrict__ b_hh_f,
                                             const float* __restrict__ b_hh_b,
                                             float* __restrict__ states){
    extern __shared__ float sm[];
    float4* hs4 = (float4*)(sm + 24576);   // h image: 32 rows x 128 float4 (64KB)

    int blk = blockIdx.x;
    int dir = blk >> 6;
    int rr = blk & 63;
    int jc = rr >> 1, bc = rr & 1;
    int jbase = jc * 16;
    int bbase = bc * 32;
    int grp = dir*2 + bc;
    const float* whh = dir ? w_hh_b : w_hh_f;
    const float* bhh = dir ? b_hh_b : b_hh_f;
    const float* xg = g_xg[dir];
    int tid = threadIdx.x;
    int jp = tid >> 4;           // 0..7
    int bp = tid & 15;           // 0..15
    int w  = jp >> 1, e = jp & 1;
    int j0 = jbase + jp*2;
    int b0 = bbase + bp*2;
    int bL0 = bp*2, bL1 = bp*2 + 1;
    unsigned key = (unsigned)(bp & 7);

    // load weights into interleaved layout:
    // float4 dst = ((g*4 + jl/4)*128 + kq)*4 + (jl&1)*2 + ((jl&3)>>1)
    {
        const float4* w4 = (const float4*)whh;
        float4* d4 = (float4*)sm;
        for (int idx = tid; idx < 48*128; idx += 128){
            int row = idx >> 7;          // g*16 + jl
            int kq = idx & 127;
            int g = row >> 4, jl = row & 15;
            int ww = jl >> 2, sub = jl & 3;
            int dst = (((g*4 + ww)*128 + kq) << 2) + ((sub & 1) << 1) + (sub >> 1);
            d4[dst] = w4[(size_t)(g*H_ + jbase + jl)*128 + kq];
        }
    }

    float2 bhr = *(const float2*)&bhh[j0];
    float2 bhz = *(const float2*)&bhh[H_+j0];
    float2 bhn = *(const float2*)&bhh[2*H_+j0];

    *(float2*)&g_h2[dir][0][(size_t)b0*H_ + j0]     = make_float2(0.f, 0.f);
    *(float2*)&g_h2[dir][0][(size_t)(b0+1)*H_ + j0] = make_float2(0.f, 0.f);
    gbar_grp(grp);

    const ulonglong2* wu = (const ulonglong2*)sm;
    int wbr = (0*4 + w)*512 + e;
    int wbz = (1*4 + w)*512 + e;
    int wbn = (2*4 + w)*512 + e;
    const ulonglong2* h0row = (const ulonglong2*)(hs4 + bL0*128);
    const ulonglong2* h1row = (const ulonglong2*)(hs4 + bL1*128);

    for (int t = 0; t < S_; t++){
        int tidx = dir ? (S_-1-t) : t;

        const float4* hr4 = (const float4*)(g_h2[dir][t & 1] + (size_t)bbase*H_);
        #pragma unroll
        for (int i = 0; i < 32; i++){
            int gi = tid + (i << 7);
            int bb = gi >> 7, kq = gi & 127;
            hs4[bb*128 + (kq ^ ((unsigned)(bb >> 1) & 7u))] = hr4[gi];
        }
        __syncthreads();

        ull ar00=0,ar01=0,ar10=0,ar11=0;
        ull az00=0,az01=0,az10=0,az11=0;
        ull an00=0,an01=0,an10=0,an11=0;
        #pragma unroll 4
        for (int kq = 0; kq < 128; kq++){
            ulonglong2 hA = h0row[kq ^ key];
            ulonglong2 hB = h1row[kq ^ key];
            int k4 = kq << 2;
            ulonglong2 w0, w1;
            w0 = wu[wbr + k4]; w1 = wu[wbr + k4 + 2];
            fma2(ar00, hA.x, w0.x); fma2(ar00, hA.y, w0.y);
            fma2(ar10, hB.x, w0.x); fma2(ar10, hB.y, w0.y);
            fma2(ar01, hA.x, w1.x); fma2(ar01, hA.y, w1.y);
            fma2(ar11, hB.x, w1.x); fma2(ar11, hB.y, w1.y);
            w0 = wu[wbz + k4]; w1 = wu[wbz + k4 + 2];
            fma2(az00, hA.x, w0.x); fma2(az00, hA.y, w0.y);
            fma2(az10, hB.x, w0.x); fma2(az10, hB.y, w0.y);
            fma2(az01, hA.x, w1.x); fma2(az01, hA.y, w1.y);
            fma2(az11, hB.x, w1.x); fma2(az11, hB.y, w1.y);
            w0 = wu[wbn + k4]; w1 = wu[wbn + k4 + 2];
            fma2(an00, hA.x, w0.x); fma2(an00, hA.y, w0.y);
            fma2(an10, hB.x, w0.x); fma2(an10, hB.y, w0.y);
            fma2(an01, hA.x, w1.x); fma2(an01, hA.y, w1.y);
            fma2(an11, hB.x, w1.x); fma2(an11, hB.y, w1.y);
        }

        int kqj = j0 >> 2, jo = j0 & 3;
        const float* hqA = (const float*)(hs4 + bL0*128 + ((unsigned)kqj ^ key));
        const float* hqB = (const float*)(hs4 + bL1*128 + ((unsigned)kqj ^ key));
        float hpA0 = hqA[jo], hpA1 = hqA[jo+1];
        float hpB0 = hqB[jo], hpB1 = hqB[jo+1];

        const float* xA = xg + ((size_t)(tidx*B_ + b0))*H3_;
        const float* xB = xA + H3_;
        float2 xrA = *(const float2*)&xA[j0];
        float2 xzA = *(const float2*)&xA[H_+j0];
        float2 xnA = *(const float2*)&xA[2*H_+j0];
        float2 xrB = *(const float2*)&xB[j0];
        float2 xzB = *(const float2*)&xB[H_+j0];
        float2 xnB = *(const float2*)&xB[2*H_+j0];

        U64F2 u;
        u.u=ar00; float srA0=u.f.x+u.f.y;  u.u=ar01; float srA1=u.f.x+u.f.y;
        u.u=ar10; float srB0=u.f.x+u.f.y;  u.u=ar11; float srB1=u.f.x+u.f.y;
        u.u=az00; float szA0=u.f.x+u.f.y;  u.u=az01; float szA1=u.f.x+u.f.y;
        u.u=az10; float szB0=u.f.x+u.f.y;  u.u=az11; float szB1=u.f.x+u.f.y;
        u.u=an00; float snA0=u.f.x+u.f.y;  u.u=an01; float snA1=u.f.x+u.f.y;
        u.u=an10; float snB0=u.f.x+u.f.y;  u.u=an11; float snB1=u.f.x+u.f.y;

        float rA0 = 1.f/(1.f+expf(-(xrA.x + srA0 + bhr.x)));
        float rA1 = 1.f/(1.f+expf(-(xrA.y + srA1 + bhr.y)));
        float rB0 = 1.f/(1.f+expf(-(xrB.x + srB0 + bhr.x)));
        float rB1 = 1.f/(1.f+expf(-(xrB.y + srB1 + bhr.y)));
        float zA0 = 1.f/(1.f+expf(-(xzA.x + szA0 + bhz.x)));
        float zA1 = 1.f/(1.f+expf(-(xzA.y + szA1 + bhz.y)));
        float zB0 = 1.f/(1.f+expf(-(xzB.x + szB0 + bhz.x)));
        float zB1 = 1.f/(1.f+expf(-(xzB.y + szB1 + bhz.y)));
        float nA0 = tanhf(xnA.x + rA0*(snA0 + bhn.x));
        float nA1 = tanhf(xnA.y + rA1*(snA1 + bhn.y));
        float nB0 = tanhf(xnB.x + rB0*(snB0 + bhn.x));
        float nB1 = tanhf(xnB.y + rB1*(snB1 + bhn.y));
        float hA0 = (1.f-zA0)*nA0 + zA0*hpA0;
        float hA1 = (1.f-zA1)*nA1 + zA1*hpA1;
        float hB0 = (1.f-zB0)*nB0 + zB0*hpB0;
        float hB1 = (1.f-zB1)*nB1 + zB1*hpB1;

        float* hw = g_h2[dir][(t & 1) ^ 1];
        *(float2*)&hw[(size_t)b0*H_ + j0]     = make_float2(hA0, hA1);
        *(float2*)&hw[(size_t)(b0+1)*H_ + j0] = make_float2(hB0, hB1);
        size_t soA = ((size_t)b0*S_ + tidx)*(2*H_) + dir*H_ + j0;
        size_t soB = ((size_t)(b0+1)*S_ + tidx)*(2*H_) + dir*H_ + j0;
        *(float2*)&states[soA] = make_float2(hA0, hA1);
        *(float2*)&states[soB] = make_float2(hB0, hB1);

        gbar_grp(grp);
    }
}

// ---------------- alpha = m1 @ att_w2^T, softmax over S -----------------------
__global__ __launch_bounds__(256) void k_alpha(const float* __restrict__ att_w2,
                                               float* __restrict__ alpha_out){
    __shared__ float w2s[NH_*A_];
    __shared__ float al[NH_*S_];
    int b = blockIdx.x, tid = threadIdx.x;
    for (int i = tid; i < NH_*A_; i += 256) w2s[i] = att_w2[i];
    __syncthreads();
    int s = tid >> 2, h = tid & 3;
    const float* m1r = g_m1 + ((size_t)(b*S_ + s))*A_;
    float acc = 0.f;
    #pragma unroll 4
    for (int k = 0; k < A_; k++) acc += m1r[k]*w2s[h*A_+k];
    al[h*S_+s] = acc;
    __syncthreads();
    int wid = tid >> 5, lane = tid & 31;
    if (wid < NH_){
        float v0 = al[wid*S_+lane], v1 = al[wid*S_+lane+32];
        float mx = fmaxf(v0, v1);
        #pragma unroll
        for (int o = 16; o > 0; o >>= 1) mx = fmaxf(mx, __shfl_xor_sync(0xffffffffu, mx, o));
        float e0 = expf(v0-mx), e1 = expf(v1-mx);
        float sm = e0 + e1;
        #pragma unroll
        for (int o = 16; o > 0; o >>= 1) sm += __shfl_xor_sync(0xffffffffu, sm, o);
        float inv = 1.f/sm;
        alpha_out[(b*NH_+wid)*S_ + lane]      = e0*inv;
        alpha_out[(b*NH_+wid)*S_ + lane + 32] = e1*inv;
    }
}

// ---------------- context = alpha @ states ------------------------------------
__global__ __launch_bounds__(512) void k_context(const float* __restrict__ states,
                                                 const float* __restrict__ alpha_in,
                                                 float* __restrict__ context){
    __shared__ float als[NH_*S_];
    int b = blockIdx.x, tid = threadIdx.x;
    if (tid < NH_*S_) als[tid] = alpha_in[b*NH_*S_ + tid];
    __syncthreads();
    float a0[NH_], a1[NH_];
    #pragma unroll
    for (int h = 0; h < NH_; h++){ a0[h] = 0.f; a1[h] = 0.f; }
    const float* st = states + (size_t)b*S_*2*H_;
    for (int s = 0; s < S_; s++){
        float v0 = st[s*2*H_ + tid];
        float v1 = st[s*2*H_ + H_ + tid];
        #pragma unroll
        for (int h = 0; h < NH_; h++){
            float a = als[h*S_+s];
            a0[h] += a*v0; a1[h] += a*v1;
        }
    }
    float* cb = context + (size_t)b*NH_*2*H_;
    #pragma unroll
    for (int h = 0; h < NH_; h++){
        cb[h*2*H_ + tid]      = a0[h];
        cb[h*2*H_ + H_ + tid] = a1[h];
    }
}

// ---------------- final linear + softmax --------------------------------------
__global__ __launch_bounds__(512) void k_final(const float* __restrict__ context,
                                               const float* __restrict__ lin_w,
                                               const float* __restrict__ lin_b,
                                               float* __restrict__ out){
    __shared__ float red[OUT_];
    int b = blockIdx.x, tid = threadIdx.x, w = tid >> 5, lane = tid & 31;
    const float* cx = context + (size_t)b*4096;
    const float* lw = lin_w + (size_t)w*4096;
    float acc = 0.f;
    for (int k = lane; k < 4096; k += 32) acc += cx[k]*lw[k];
    #pragma unroll
    for (int o = 16; o > 0; o >>= 1) acc += __shfl_xor_sync(0xffffffffu, acc, o);
    if (lane == 0) red[w] = acc + lin_b[w];
    __syncthreads();
    if (tid < 32){
        float v = (lane < OUT_) ? red[lane] : -1e30f;
        float mx = v;
        #pragma unroll
        for (int o = 16; o > 0; o >>= 1) mx = fmaxf(mx, __shfl_xor_sync(0xffffffffu, mx, o));
        float e = (lane < OUT_) ? expf(v - mx) : 0.f;
        float sm = e;
        #pragma unroll
        for (int o = 16; o > 0; o >>= 1) sm += __shfl_xor_sync(0xffffffffu, sm, o);
        if (lane < OUT_) out[b*OUT_ + lane] = e/sm;
    }
}

// ---------------- launch ------------------------------------------------------
extern "C" void kernel_launch(void* const* d_in, const int* in_sizes, int n_in,
                              void* d_out, int out_size){
    const float* inputs  = (const float*)d_in[0];
    const float* conv_w  = (const float*)d_in[2];
    const float* conv_b  = (const float*)d_in[3];
    const float* w_embed = (const float*)d_in[4];
    const float* w_ih_f  = (const float*)d_in[5];
    const float* w_hh_f  = (const float*)d_in[6];
    const float* b_ih_f  = (const float*)d_in[7];
    const float* b_hh_f  = (const float*)d_in[8];
    const float* w_ih_b  = (const float*)d_in[9];
    const float* w_hh_b  = (const float*)d_in[10];
    const float* b_ih_b  = (const float*)d_in[11];
    const float* b_hh_b  = (const float*)d_in[12];
    const float* att_w1  = (const float*)d_in[13];
    const float* att_w2  = (const float*)d_in[14];
    const float* lin_w   = (const float*)d_in[15];
    const float* lin_b   = (const float*)d_in[16];

    float* out     = (float*)d_out;
    float* states  = out + STATES_OFF;
    float* context = out + CONTEXT_OFF;
    float* alpha   = out + ALPHA_OFF;

    void *p_vec, *p_emb, *p_xg, *p_m1;
    cudaGetSymbolAddress(&p_vec, g_vec);
    cudaGetSymbolAddress(&p_emb, g_emb);
    cudaGetSymbolAddress(&p_xg,  g_xg);
    cudaGetSymbolAddress(&p_m1,  g_m1);
    float* vec = (float*)p_vec;
    float* emb = (float*)p_emb;
    float* xg0 = (float*)p_xg;
    float* xg1 = xg0 + (size_t)BS_*H3_;
    float* m1  = (float*)p_m1;

    const int conv_smem = P_*D_*4;                     // 65536
    const int gru_smem  = 24576*4 + 32*128*16;         // 96KB + 64KB = 163840
    cudaFuncSetAttribute(k_conv_vec, cudaFuncAttributeMaxDynamicSharedMemorySize, conv_smem);
    cudaFuncSetAttribute(k_gru,      cudaFuncAttributeMaxDynamicSharedMemorySize, gru_smem);

    // 1) conv + weighted-sum (inputs read once)
    k_conv_vec<<<BS_, 256, conv_smem>>>(inputs, conv_w, conv_b);
    // 2) emb = clip(vec @ w_embed^T)
    k_sgemm<<<dim3(E_/128, BS_/128), 256>>>(vec, w_embed, emb, BS_, E_, D_, nullptr, 1, 0);
    // 3) xg = emb([S,B] permuted) @ w_ih^T + b_ih, both directions
    k_sgemm<<<dim3(H3_/128, BS_/128), 256>>>(emb, w_ih_f, xg0, BS_, H3_, E_, b_ih_f, 0, 1);
    k_sgemm<<<dim3(H3_/128, BS_/128), 256>>>(emb, w_ih_b, xg1, BS_, H3_, E_, b_ih_b, 0, 1);
    // 4) persistent bidirectional GRU -> states (written straight into d_out)
    k_gru<<<128, 128, gru_smem>>>(w_hh_f, w_hh_b, b_hh_f, b_hh_b, states);
    // 5) m1 = clip(states @ att_w1^T)
    k_sgemm<<<dim3(A_/128, BS_/128), 256>>>(states, att_w1, m1, BS_, A_, 2*H_, nullptr, 1, 0);
    // 6) alpha = softmax_S(m1 @ att_w2^T), transposed to [B,NH,S]
    k_alpha<<<B_, 256>>>(att_w2, alpha);
    // 7) context
    k_context<<<B_, 512>>>(states, alpha, context);
    // 8) out = softmax(context @ lin_w^T + lin_b)
    k_final<<<B_, 512>>>(context, lin_w, lin_b, out);
}